// round 13
// baseline (speedup 1.0000x reference)
#include <cuda_runtime.h>
#include <cuda_bf16.h>
#include <cuda_fp16.h>
#include <math.h>
#include <stdint.h>

// Problem constants
#define N_NODES 50000
#define N_EDGES 800000
#define F_IN    128
#define F_HID   256
#define F_OUT   64

#define GSYNC_BLOCKS 296   // 2 per SM, guaranteed co-resident

// ---------------- scratch (static __device__; no allocation) -----------------
__device__ int      g_deg[N_NODES];
__device__ int      g_off[N_NODES + 1];
__device__ int      g_cur[N_NODES];
__device__ int      g_csr[N_EDGES];
__device__ int      g_bsum[GSYNC_BLOCKS];
__device__ int      g_boff[GSYNC_BLOCKS];
__device__ unsigned g_barc;               // monotonic grid-barrier counter
// fp16 copy of x for gathers, [N][128] halves = 32 uint2 per row
__device__ uint2 g_xh2[(size_t)N_NODES * 32];
// Layer-1 A = [agg1 | x] pre-split to bf16 hi/lo, [M][256]
__device__ __nv_bfloat16 g_A1hi[(size_t)N_NODES * 256];
__device__ __nv_bfloat16 g_A1lo[(size_t)N_NODES * 256];
// Layer-2 A = h (relu hidden) pre-split to bf16 hi/lo, [M][256]
__device__ __nv_bfloat16 g_A2hi[(size_t)N_NODES * 256];
__device__ __nv_bfloat16 g_A2lo[(size_t)N_NODES * 256];
__device__ uint2 g_t2[(size_t)N_NODES * 16];     // h @ W_l2, fp16 [N][64]
__device__ float g_u[(size_t)N_NODES * F_OUT];   // h @ W_r2, fp32
// pre-split / transposed / stacked weights (bf16 hi+lo), [N][K] k-contiguous
__device__ __nv_bfloat16 g_Bt1_hi[256 * 256];
__device__ __nv_bfloat16 g_Bt1_lo[256 * 256];
__device__ __nv_bfloat16 g_Bt2_hi[128 * 256];
__device__ __nv_bfloat16 g_Bt2_lo[128 * 256];

// ---------------- helpers ----------------------------------------------------
__device__ __forceinline__ uint32_t smem_u32(const void* p) {
    uint32_t a;
    asm("{ .reg .u64 t; cvta.to.shared.u64 t, %1; cvt.u32.u64 %0, t; }" : "=r"(a) : "l"(p));
    return a;
}
__device__ __forceinline__ uint32_t sw64(uint32_t off) { return off ^ ((off >> 3) & 0x30); }

__device__ __forceinline__ uint32_t pack2(__nv_bfloat16 a, __nv_bfloat16 b) {
    return (uint32_t)__bfloat16_as_ushort(a) | ((uint32_t)__bfloat16_as_ushort(b) << 16);
}
__device__ __forceinline__ void split4(float4 v, uint2& hi, uint2& lo) {
    __nv_bfloat16 h0 = __float2bfloat16(v.x), h1 = __float2bfloat16(v.y);
    __nv_bfloat16 h2 = __float2bfloat16(v.z), h3 = __float2bfloat16(v.w);
    __nv_bfloat16 l0 = __float2bfloat16(v.x - __bfloat162float(h0));
    __nv_bfloat16 l1 = __float2bfloat16(v.y - __bfloat162float(h1));
    __nv_bfloat16 l2 = __float2bfloat16(v.z - __bfloat162float(h2));
    __nv_bfloat16 l3 = __float2bfloat16(v.w - __bfloat162float(h3));
    hi.x = pack2(h0, h1); hi.y = pack2(h2, h3);
    lo.x = pack2(l0, l1); lo.y = pack2(l2, l3);
}
__device__ __forceinline__ uint2 pack_f4_to_h4(float4 v) {
    __half2 p0 = __float22half2_rn(make_float2(v.x, v.y));
    __half2 p1 = __float22half2_rn(make_float2(v.z, v.w));
    uint2 r;
    r.x = *reinterpret_cast<uint32_t*>(&p0);
    r.y = *reinterpret_cast<uint32_t*>(&p1);
    return r;
}
__device__ __forceinline__ float4 unpack_h4(uint2 q) {
    __half2 h0 = *reinterpret_cast<__half2*>(&q.x);
    __half2 h1 = *reinterpret_cast<__half2*>(&q.y);
    float2 f0 = __half22float2(h0);
    float2 f1 = __half22float2(h1);
    return make_float4(f0.x, f0.y, f1.x, f1.y);
}

#define CP_ASYNC16(dst, src, sz) \
    asm volatile("cp.async.cg.shared.global [%0], [%1], 16, %2;" \
                 :: "r"(dst), "l"(src), "r"(sz) : "memory")
#define CP_COMMIT() asm volatile("cp.async.commit_group;" ::: "memory")
#define CP_WAIT(n)  asm volatile("cp.async.wait_group %0;" :: "n"(n) : "memory")

#define LDSM4(r, addr) \
    asm volatile("ldmatrix.sync.aligned.m8n8.x4.shared.b16 {%0,%1,%2,%3}, [%4];" \
                 : "=r"((r)[0]), "=r"((r)[1]), "=r"((r)[2]), "=r"((r)[3]) : "r"(addr))

#define MMA_BF16(d, a, b0, b1) \
    asm volatile("mma.sync.aligned.m16n8k16.row.col.f32.bf16.bf16.f32 " \
                 "{%0,%1,%2,%3}, {%4,%5,%6,%7}, {%8,%9}, {%0,%1,%2,%3};" \
                 : "+f"((d)[0]), "+f"((d)[1]), "+f"((d)[2]), "+f"((d)[3]) \
                 : "r"((a)[0]), "r"((a)[1]), "r"((a)[2]), "r"((a)[3]), "r"(b0), "r"(b1))

// Monotonic-counter grid barrier (counter never reset; wrap unreachable).
__device__ __forceinline__ void grid_sync() {
    __syncthreads();
    if (threadIdx.x == 0) {
        __threadfence();
        unsigned arrive = atomicAdd(&g_barc, 1) + 1;
        unsigned target = ((arrive + GSYNC_BLOCKS - 1) / GSYNC_BLOCKS) * GSYNC_BLOCKS;
        while (atomicAdd(&g_barc, 0) < target) __nanosleep(64);
        __threadfence();
    }
    __syncthreads();
}

// ---------------- CSR build + weight prep + x->fp16: one persistent kernel ---
__global__ __launch_bounds__(256)
void csr_coop_kernel(const int* __restrict__ src, const int* __restrict__ dst,
                     const float* __restrict__ x,
                     const float* __restrict__ W_l1, const float* __restrict__ W_r1,
                     const float* __restrict__ W_l2, const float* __restrict__ W_r2,
                     int e, int n)
{
    const int G = GSYNC_BLOCKS;
    const int b = blockIdx.x, t = threadIdx.x;
    const int gid = b * 256 + t, gstride = G * 256;
    __shared__ int sh[256];
    __shared__ int sb[GSYNC_BLOCKS];

    for (int i = gid; i < n; i += gstride) g_deg[i] = 0;
    grid_sync();

    // phase 1: count + weight prep + x fp16 copy (independent work, overlapped)
    int n4 = e >> 2;
    for (int i = gid; i < n4; i += gstride) {
        int4 d = __ldg((const int4*)dst + i);
        atomicAdd(&g_deg[d.x], 1);
        atomicAdd(&g_deg[d.y], 1);
        atomicAdd(&g_deg[d.z], 1);
        atomicAdd(&g_deg[d.w], 1);
    }
    if (gid < (e & 3)) atomicAdd(&g_deg[dst[n4 * 4 + gid]], 1);
    for (int i = gid; i < n * 32; i += gstride) {
        float4 v = __ldg((const float4*)x + i);
        g_xh2[i] = pack_f4_to_h4(v);
    }
    for (int i = gid; i < 256 * 256 + 128 * 256; i += gstride) {
        if (i < 256 * 256) {
            int nn = i >> 8, k = i & 255;
            float w = (k < 128) ? W_l1[(size_t)k * 256 + nn] : W_r1[(size_t)(k - 128) * 256 + nn];
            __nv_bfloat16 hi = __float2bfloat16(w);
            __nv_bfloat16 lo = __float2bfloat16(w - __bfloat162float(hi));
            g_Bt1_hi[i] = hi;
            g_Bt1_lo[i] = lo;
        } else {
            int j = i - 256 * 256;
            int nn = j >> 8, k = j & 255;
            float w = (nn < 64) ? W_l2[(size_t)k * 64 + nn] : W_r2[(size_t)k * 64 + (nn - 64)];
            __nv_bfloat16 hi = __float2bfloat16(w);
            __nv_bfloat16 lo = __float2bfloat16(w - __bfloat162float(hi));
            g_Bt2_hi[j] = hi;
            g_Bt2_lo[j] = lo;
        }
    }
    grid_sync();

    int Lb = (n + G - 1) / G;
    int node = b * Lb + t;
    int deg = (t < Lb && node < n) ? g_deg[node] : 0;
    sh[t] = deg;
    __syncthreads();
    for (int s = 1; s < 256; s <<= 1) {
        int v = (t >= s) ? sh[t - s] : 0;
        __syncthreads();
        sh[t] += v;
        __syncthreads();
    }
    int ex = sh[t] - deg;
    if (t == 255) g_bsum[b] = sh[255];
    grid_sync();

    if (b == 0) {
        for (int i = t; i < G; i += 256) sb[i] = g_bsum[i];
        __syncthreads();
        for (int i = t; i < G; i += 256) {
            int acc = 0;
            for (int k = 0; k < i; k++) acc += sb[k];
            g_boff[i] = acc;
        }
    }
    grid_sync();

    int boff = g_boff[b];
    if (t < Lb && node < n) {
        g_off[node] = boff + ex;
        g_cur[node] = boff + ex;
    }
    if (b == G - 1 && t == 0) g_off[n] = g_boff[G - 1] + g_bsum[G - 1];
    grid_sync();

    for (int i = gid; i < n4; i += gstride) {
        int4 d = __ldg((const int4*)dst + i);
        int4 s = __ldg((const int4*)src + i);
        g_csr[atomicAdd(&g_cur[d.x], 1)] = s.x;
        g_csr[atomicAdd(&g_cur[d.y], 1)] = s.y;
        g_csr[atomicAdd(&g_cur[d.z], 1)] = s.z;
        g_csr[atomicAdd(&g_cur[d.w], 1)] = s.w;
    }
    if (gid < (e & 3)) {
        int j = n4 * 4 + gid;
        g_csr[atomicAdd(&g_cur[dst[j]], 1)] = src[j];
    }
}

// ---------------- layer-1 aggregation (fp16 gathers) + x convert -------------
__global__ void agg128_kernel(const float* __restrict__ x) {
    int w = (blockIdx.x * blockDim.x + threadIdx.x) >> 5;
    int lane = threadIdx.x & 31;
    if (w >= N_NODES) return;
    int s = g_off[w], e = g_off[w + 1];
    float4 a0 = make_float4(0.f, 0.f, 0.f, 0.f), a1 = a0, a2 = a0, a3 = a0;
    int i = s;
    for (; i + 4 <= e; i += 4) {
        int s0 = g_csr[i], s1 = g_csr[i + 1], s2 = g_csr[i + 2], s3 = g_csr[i + 3];
        float4 v0 = unpack_h4(__ldg(&g_xh2[(size_t)s0 * 32 + lane]));
        float4 v1 = unpack_h4(__ldg(&g_xh2[(size_t)s1 * 32 + lane]));
        float4 v2 = unpack_h4(__ldg(&g_xh2[(size_t)s2 * 32 + lane]));
        float4 v3 = unpack_h4(__ldg(&g_xh2[(size_t)s3 * 32 + lane]));
        a0.x += v0.x; a0.y += v0.y; a0.z += v0.z; a0.w += v0.w;
        a1.x += v1.x; a1.y += v1.y; a1.z += v1.z; a1.w += v1.w;
        a2.x += v2.x; a2.y += v2.y; a2.z += v2.z; a2.w += v2.w;
        a3.x += v3.x; a3.y += v3.y; a3.z += v3.z; a3.w += v3.w;
    }
    for (; i < e; i++) {
        int sn = g_csr[i];
        float4 v = unpack_h4(__ldg(&g_xh2[(size_t)sn * 32 + lane]));
        a0.x += v.x; a0.y += v.y; a0.z += v.z; a0.w += v.w;
    }
    float4 acc;
    acc.x = (a0.x + a1.x) + (a2.x + a3.x);
    acc.y = (a0.y + a1.y) + (a2.y + a3.y);
    acc.z = (a0.z + a1.z) + (a2.z + a3.z);
    acc.w = (a0.w + a1.w) + (a2.w + a3.w);
    float inv = (e > s) ? 1.0f / (float)(e - s) : 0.0f;
    acc.x *= inv; acc.y *= inv; acc.z *= inv; acc.w *= inv;
    uint2 hi, lo;
    split4(acc, hi, lo);
    *(uint2*)(g_A1hi + (size_t)w * 256 + lane * 4) = hi;
    *(uint2*)(g_A1lo + (size_t)w * 256 + lane * 4) = lo;
    // self term keeps full fp32 precision
    float4 xv = __ldg(((const float4*)(x + (size_t)w * F_IN)) + lane);
    split4(xv, hi, lo);
    *(uint2*)(g_A1hi + (size_t)w * 256 + 128 + lane * 4) = hi;
    *(uint2*)(g_A1lo + (size_t)w * 256 + 128 + lane * 4) = lo;
}

// layer 2: mean of t (fp16 gathers) fused with sigmoid epilogue
__global__ void agg64_final_kernel(const float* __restrict__ b2, float* __restrict__ out) {
    int w = (blockIdx.x * blockDim.x + threadIdx.x) >> 5;
    int lane = threadIdx.x & 31;
    if (w >= N_NODES) return;
    int s = g_off[w], e = g_off[w + 1];
    const __half2* tp = reinterpret_cast<const __half2*>(g_t2);
    float2 a0 = make_float2(0.f, 0.f), a1 = a0, a2 = a0, a3 = a0;
    int i = s;
    for (; i + 4 <= e; i += 4) {
        int s0 = g_csr[i], s1 = g_csr[i + 1], s2 = g_csr[i + 2], s3 = g_csr[i + 3];
        float2 v0 = __half22float2(__ldg(tp + (size_t)s0 * 32 + lane));
        float2 v1 = __half22float2(__ldg(tp + (size_t)s1 * 32 + lane));
        float2 v2 = __half22float2(__ldg(tp + (size_t)s2 * 32 + lane));
        float2 v3 = __half22float2(__ldg(tp + (size_t)s3 * 32 + lane));
        a0.x += v0.x; a0.y += v0.y;
        a1.x += v1.x; a1.y += v1.y;
        a2.x += v2.x; a2.y += v2.y;
        a3.x += v3.x; a3.y += v3.y;
    }
    for (; i < e; i++) {
        int sn = g_csr[i];
        float2 v = __half22float2(__ldg(tp + (size_t)sn * 32 + lane));
        a0.x += v.x; a0.y += v.y;
    }
    float2 acc;
    acc.x = (a0.x + a1.x) + (a2.x + a3.x);
    acc.y = (a0.y + a1.y) + (a2.y + a3.y);
    float inv = (e > s) ? 1.0f / (float)(e - s) : 0.0f;
    float2 u = *(const float2*)(g_u + (size_t)w * F_OUT + lane * 2);
    float bx = __ldg(&b2[lane * 2]);
    float by = __ldg(&b2[lane * 2 + 1]);
    float vx = acc.x * inv + u.x + bx;
    float vy = acc.y * inv + u.y + by;
    float2 o;
    o.x = 1.f / (1.f + __expf(-vx));
    o.y = 1.f / (1.f + __expf(-vy));
    *(float2*)(out + (size_t)w * F_OUT + lane * 2) = o;
}

// ---------------- bf16-split GEMM, 128x64 tiles, 3 CTAs/SM -------------------
// C[128,64] tile = A[128,256] @ Bt[colBase:+64, 256]^T ; 3-term bf16 split.
// 256 threads / 8 warps (4M x 2N), warp tile 32x32. K-chunks of 32 (SW64),
// 3-stage cp.async pipeline.
// MODE 1: v = relu(C + bias[col]); store bf16 hi/lo to oHi/oLo [M][256]
// MODE 2: blockIdx.y==0 -> t2 fp16 [M][64]; ==1 -> uF fp32 [M][64]
#define SM_BUF    24576   // Ahi 8K | Alo 8K | Bhi 4K | Blo 4K
#define SMEM_GEMM 73728   // 3 stages

template <int MODE>
__global__ __launch_bounds__(256, 3)
void gemm_mma_kernel(const __nv_bfloat16* __restrict__ Ahi, const __nv_bfloat16* __restrict__ Alo,
                     const __nv_bfloat16* __restrict__ Bhi, const __nv_bfloat16* __restrict__ Blo,
                     const float* __restrict__ bias,
                     __nv_bfloat16* __restrict__ oHi, __nv_bfloat16* __restrict__ oLo,
                     uint2* __restrict__ t2out, float* __restrict__ uF, int M)
{
    extern __shared__ __align__(128) char sm[];
    const uint32_t sb = smem_u32(sm);
    const int tid  = threadIdx.x;
    const int wid  = tid >> 5;
    const int lane = tid & 31;
    const int wm = (wid & 3) * 32;    // 4 warps along M
    const int wn = (wid >> 2) * 32;   // 2 warps along N
    const int rowBase = blockIdx.x * 128;
    const int colBase = blockIdx.y * 64;

    float acc[2][4][4];
#pragma unroll
    for (int a = 0; a < 2; a++)
#pragma unroll
        for (int b = 0; b < 4; b++)
#pragma unroll
            for (int c = 0; c < 4; c++) acc[a][b][c] = 0.f;

    // chunk loader: k-cols [c*32,+32) of A rows [rowBase,+128), B rows [colBase,+64)
    auto issue = [&](int c, int buf) {
        uint32_t base = sb + buf * SM_BUF;
#pragma unroll
        for (int i = tid; i < 512; i += 256) {
            int r = i >> 2, j = i & 3;            // j: which 16B of the 64B row
            uint32_t off = sw64((uint32_t)(r * 64 + j * 16));
            int arow = rowBase + r;
            int asz = (arow < M) ? 16 : 0;
            size_t aidx = (size_t)min(arow, M - 1) * 256 + c * 32 + j * 8;
            CP_ASYNC16(base + off,         (const char*)(Ahi + aidx), asz);
            CP_ASYNC16(base + 8192 + off,  (const char*)(Alo + aidx), asz);
        }
        {
            int r = tid >> 2, j = tid & 3;        // B: 64 rows x 64B
            uint32_t off = sw64((uint32_t)(r * 64 + j * 16));
            size_t bidx = (size_t)(colBase + r) * 256 + c * 32 + j * 8;
            CP_ASYNC16(base + 16384 + off, (const char*)(Bhi + bidx), 16);
            CP_ASYNC16(base + 20480 + off, (const char*)(Blo + bidx), 16);
        }
        CP_COMMIT();
    };

    issue(0, 0);
    issue(1, 1);
#pragma unroll 1
    for (int c = 0; c < 8; c++) {
        if (c < 7) { CP_WAIT(1); } else { CP_WAIT(0); }
        __syncthreads();                 // publishes stage c; proves stage (c+2)%3 free
        if (c < 6) issue(c + 2, (c + 2) % 3);
        uint32_t base = sb + (c % 3) * SM_BUF;

        const int t = lane >> 3, rIn = lane & 7;
        const int rowAdd = rIn + (t & 1) * 8;
        const int kAdd = (t >> 1) * 16;   // bytes
#pragma unroll
        for (int ks = 0; ks < 2; ks++) {
            int kB = ks * 32 + kAdd;
            uint32_t ah[2][4], al[2][4];
#pragma unroll
            for (int mt = 0; mt < 2; mt++) {
                uint32_t ad = base + sw64((uint32_t)((wm + mt * 16 + rowAdd) * 64 + kB));
                LDSM4(ah[mt], ad);
                LDSM4(al[mt], ad + 8192);
            }
#pragma unroll
            for (int n4 = 0; n4 < 2; n4++) {
                uint32_t bh[4], bl[4];
                uint32_t bd = base + 16384 + sw64((uint32_t)((wn + n4 * 16 + rowAdd) * 64 + kB));
                LDSM4(bh, bd);
                LDSM4(bl, bd + 4096);
#pragma unroll
                for (int hf = 0; hf < 2; hf++) {
                    int nt = n4 * 2 + hf;
                    MMA_BF16(acc[0][nt], ah[0], bh[hf], bh[hf + 2]);
                    MMA_BF16(acc[1][nt], ah[1], bh[hf], bh[hf + 2]);
                    MMA_BF16(acc[0][nt], ah[0], bl[hf], bl[hf + 2]);
                    MMA_BF16(acc[1][nt], ah[1], bl[hf], bl[hf + 2]);
                    MMA_BF16(acc[0][nt], al[0], bh[hf], bh[hf + 2]);
                    MMA_BF16(acc[1][nt], al[1], bh[hf], bh[hf + 2]);
                }
            }
        }
        // next iteration's CP_WAIT+sync provides the barrier
    }
    __syncthreads();

    // ---- epilogue: stage through smem (68-float stride), coalesced stores ---
    float* sep = (float*)sm;   // 128 x 68 fp32 = 34816 B <= 72KB
    const int g = lane >> 2, cp2 = (lane & 3) * 2;
#pragma unroll
    for (int mt = 0; mt < 2; mt++)
#pragma unroll
        for (int nt = 0; nt < 4; nt++) {
            int r0 = wm + mt * 16 + g;
            int cc = wn + nt * 8 + cp2;
            float v0 = acc[mt][nt][0], v1 = acc[mt][nt][1];
            float v2 = acc[mt][nt][2], v3 = acc[mt][nt][3];
            if (MODE == 1) {
                float bA = __ldg(&bias[colBase + cc]);
                float bB = __ldg(&bias[colBase + cc + 1]);
                v0 = fmaxf(v0 + bA, 0.f); v1 = fmaxf(v1 + bB, 0.f);
                v2 = fmaxf(v2 + bA, 0.f); v3 = fmaxf(v3 + bB, 0.f);
            }
            sep[r0 * 68 + cc] = v0;       sep[r0 * 68 + cc + 1] = v1;
            sep[(r0 + 8) * 68 + cc] = v2; sep[(r0 + 8) * 68 + cc + 1] = v3;
        }
    __syncthreads();
#pragma unroll 1
    for (int i = tid; i < 128 * 16; i += 256) {
        int r = i >> 4, c4 = (i & 15) * 4;
        int row = rowBase + r;
        if (row < M) {
            float4 v = *(const float4*)&sep[r * 68 + c4];
            if (MODE == 1) {
                uint2 hi, lo;
                split4(v, hi, lo);
                size_t o = (size_t)row * 256 + colBase + c4;
                *(uint2*)(oHi + o) = hi;
                *(uint2*)(oLo + o) = lo;
            } else {
                if (blockIdx.y == 0) t2out[(size_t)row * 16 + (c4 >> 2)] = pack_f4_to_h4(v);
                else                 *(float4*)(uF + (size_t)row * 64 + c4) = v;
            }
        }
    }
}

// ---------------- launch -----------------------------------------------------
extern "C" void kernel_launch(void* const* d_in, const int* in_sizes, int n_in,
                              void* d_out, int out_size)
{
    const float* x    = (const float*)d_in[0];
    const int*   ei   = (const int*)  d_in[1];
    const float* W_l1 = (const float*)d_in[2];
    const float* W_r1 = (const float*)d_in[3];
    const float* b1   = (const float*)d_in[4];
    const float* W_l2 = (const float*)d_in[5];
    const float* W_r2 = (const float*)d_in[6];
    const float* b2   = (const float*)d_in[7];
    float*       out  = (float*)d_out;

    int n = in_sizes[0] / F_IN;
    int e = in_sizes[1] / 2;
    const int* srcp = ei;
    const int* dstp = ei + e;

    __nv_bfloat16 *a1h, *a1l, *a2h, *a2l, *bt1h, *bt1l, *bt2h, *bt2l;
    uint2* t2_p;
    float* u_p;
    cudaGetSymbolAddress((void**)&a1h,  g_A1hi);
    cudaGetSymbolAddress((void**)&a1l,  g_A1lo);
    cudaGetSymbolAddress((void**)&a2h,  g_A2hi);
    cudaGetSymbolAddress((void**)&a2l,  g_A2lo);
    cudaGetSymbolAddress((void**)&bt1h, g_Bt1_hi);
    cudaGetSymbolAddress((void**)&bt1l, g_Bt1_lo);
    cudaGetSymbolAddress((void**)&bt2h, g_Bt2_hi);
    cudaGetSymbolAddress((void**)&bt2l, g_Bt2_lo);
    cudaGetSymbolAddress((void**)&t2_p, g_t2);
    cudaGetSymbolAddress((void**)&u_p,  g_u);

    cudaFuncSetAttribute(gemm_mma_kernel<1>, cudaFuncAttributeMaxDynamicSharedMemorySize, SMEM_GEMM);
    cudaFuncSetAttribute(gemm_mma_kernel<2>, cudaFuncAttributeMaxDynamicSharedMemorySize, SMEM_GEMM);

    int mtiles = (n + 127) / 128;

    // CSR build + weight prep + x fp16 copy (fused persistent kernel)
    csr_coop_kernel<<<GSYNC_BLOCKS, 256>>>(srcp, dstp, x, W_l1, W_r1, W_l2, W_r2, e, n); // 0
    // layer-1 aggregation (fp16 gathers) + x convert
    agg128_kernel<<<(n * 32 + 255) / 256, 256>>>(x);                     // 1
    // h = relu([agg1|x] @ [W_l1;W_r1] + b1) -> A2 hi/lo
    gemm_mma_kernel<1><<<dim3(mtiles, 4), 256, SMEM_GEMM>>>(a1h, a1l, bt1h, bt1l, b1,
                                                            a2h, a2l, nullptr, nullptr, n); // 2
    // [t|u] = h @ [W_l2|W_r2]; t stored fp16
    gemm_mma_kernel<2><<<dim3(mtiles, 2), 256, SMEM_GEMM>>>(a2h, a2l, bt2h, bt2l, nullptr,
                                                            nullptr, nullptr, t2_p, u_p, n); // 3 (profiled)
    // layer-2 aggregation of t (fp16 gathers) + sigmoid epilogue
    agg64_final_kernel<<<(n * 32 + 255) / 256, 256>>>(b2, out);          // 4
}

// round 14
// speedup vs baseline: 1.0185x; 1.0185x over previous
#include <cuda_runtime.h>
#include <cuda_bf16.h>
#include <math.h>
#include <stdint.h>

// Problem constants
#define N_NODES 50000
#define N_EDGES 800000
#define F_IN    128
#define F_HID   256
#define F_OUT   64

#define GSYNC_BLOCKS 296   // 2 per SM, guaranteed co-resident

// ---------------- scratch (static __device__; no allocation) -----------------
__device__ int      g_deg[N_NODES];
__device__ int      g_off[N_NODES + 1];
__device__ int      g_cur[N_NODES];
__device__ int      g_csr[N_EDGES];
__device__ int      g_bsum[GSYNC_BLOCKS];
__device__ int      g_boff[GSYNC_BLOCKS];
__device__ unsigned g_barc;               // monotonic grid-barrier counter
// Layer-1 A = [agg1 | x] pre-split to bf16 hi/lo, [M][256]
__device__ __nv_bfloat16 g_A1hi[(size_t)N_NODES * 256];
__device__ __nv_bfloat16 g_A1lo[(size_t)N_NODES * 256];
// Layer-2 A = h (relu hidden) pre-split to bf16 hi/lo, [M][256]
__device__ __nv_bfloat16 g_A2hi[(size_t)N_NODES * 256];
__device__ __nv_bfloat16 g_A2lo[(size_t)N_NODES * 256];
__device__ float g_t[(size_t)N_NODES * F_OUT];   // h @ W_l2
__device__ float g_u[(size_t)N_NODES * F_OUT];   // h @ W_r2
// pre-split / transposed / stacked weights (bf16 hi+lo), [N][K] k-contiguous
__device__ __nv_bfloat16 g_Bt1_hi[256 * 256];
__device__ __nv_bfloat16 g_Bt1_lo[256 * 256];
__device__ __nv_bfloat16 g_Bt2_hi[128 * 256];
__device__ __nv_bfloat16 g_Bt2_lo[128 * 256];

// ---------------- helpers ----------------------------------------------------
__device__ __forceinline__ uint32_t smem_u32(const void* p) {
    uint32_t a;
    asm("{ .reg .u64 t; cvta.to.shared.u64 t, %1; cvt.u32.u64 %0, t; }" : "=r"(a) : "l"(p));
    return a;
}
__device__ __forceinline__ uint32_t sw64(uint32_t off) { return off ^ ((off >> 3) & 0x30); }

__device__ __forceinline__ uint32_t pack2(__nv_bfloat16 a, __nv_bfloat16 b) {
    return (uint32_t)__bfloat16_as_ushort(a) | ((uint32_t)__bfloat16_as_ushort(b) << 16);
}
__device__ __forceinline__ void split4(float4 v, uint2& hi, uint2& lo) {
    __nv_bfloat16 h0 = __float2bfloat16(v.x), h1 = __float2bfloat16(v.y);
    __nv_bfloat16 h2 = __float2bfloat16(v.z), h3 = __float2bfloat16(v.w);
    __nv_bfloat16 l0 = __float2bfloat16(v.x - __bfloat162float(h0));
    __nv_bfloat16 l1 = __float2bfloat16(v.y - __bfloat162float(h1));
    __nv_bfloat16 l2 = __float2bfloat16(v.z - __bfloat162float(h2));
    __nv_bfloat16 l3 = __float2bfloat16(v.w - __bfloat162float(h3));
    hi.x = pack2(h0, h1); hi.y = pack2(h2, h3);
    lo.x = pack2(l0, l1); lo.y = pack2(l2, l3);
}

#define CP_ASYNC16(dst, src, sz) \
    asm volatile("cp.async.cg.shared.global [%0], [%1], 16, %2;" \
                 :: "r"(dst), "l"(src), "r"(sz) : "memory")
#define CP_COMMIT() asm volatile("cp.async.commit_group;" ::: "memory")
#define CP_WAIT(n)  asm volatile("cp.async.wait_group %0;" :: "n"(n) : "memory")

#define LDSM4(r, addr) \
    asm volatile("ldmatrix.sync.aligned.m8n8.x4.shared.b16 {%0,%1,%2,%3}, [%4];" \
                 : "=r"((r)[0]), "=r"((r)[1]), "=r"((r)[2]), "=r"((r)[3]) : "r"(addr))

#define MMA_BF16(d, a, b0, b1) \
    asm volatile("mma.sync.aligned.m16n8k16.row.col.f32.bf16.bf16.f32 " \
                 "{%0,%1,%2,%3}, {%4,%5,%6,%7}, {%8,%9}, {%0,%1,%2,%3};" \
                 : "+f"((d)[0]), "+f"((d)[1]), "+f"((d)[2]), "+f"((d)[3]) \
                 : "r"((a)[0]), "r"((a)[1]), "r"((a)[2]), "r"((a)[3]), "r"(b0), "r"(b1))

// Monotonic-counter grid barrier (counter never reset; wrap unreachable).
__device__ __forceinline__ void grid_sync() {
    __syncthreads();
    if (threadIdx.x == 0) {
        __threadfence();
        unsigned arrive = atomicAdd(&g_barc, 1) + 1;
        unsigned target = ((arrive + GSYNC_BLOCKS - 1) / GSYNC_BLOCKS) * GSYNC_BLOCKS;
        while (atomicAdd(&g_barc, 0) < target) __nanosleep(64);
        __threadfence();
    }
    __syncthreads();
}

// ---------------- CSR build + weight prep: one persistent kernel -------------
__global__ __launch_bounds__(256)
void csr_coop_kernel(const int* __restrict__ src, const int* __restrict__ dst,
                     const float* __restrict__ W_l1, const float* __restrict__ W_r1,
                     const float* __restrict__ W_l2, const float* __restrict__ W_r2,
                     int e, int n)
{
    const int G = GSYNC_BLOCKS;
    const int b = blockIdx.x, t = threadIdx.x;
    const int gid = b * 256 + t, gstride = G * 256;
    __shared__ int sh[256];
    __shared__ int sb[GSYNC_BLOCKS];

    for (int i = gid; i < n; i += gstride) g_deg[i] = 0;
    grid_sync();

    // phase 1: count + weight prep (independent work, overlapped)
    int n4 = e >> 2;
    for (int i = gid; i < n4; i += gstride) {
        int4 d = __ldg((const int4*)dst + i);
        atomicAdd(&g_deg[d.x], 1);
        atomicAdd(&g_deg[d.y], 1);
        atomicAdd(&g_deg[d.z], 1);
        atomicAdd(&g_deg[d.w], 1);
    }
    if (gid < (e & 3)) atomicAdd(&g_deg[dst[n4 * 4 + gid]], 1);
    for (int i = gid; i < 256 * 256 + 128 * 256; i += gstride) {
        if (i < 256 * 256) {
            int nn = i >> 8, k = i & 255;
            float w = (k < 128) ? W_l1[(size_t)k * 256 + nn] : W_r1[(size_t)(k - 128) * 256 + nn];
            __nv_bfloat16 hi = __float2bfloat16(w);
            __nv_bfloat16 lo = __float2bfloat16(w - __bfloat162float(hi));
            g_Bt1_hi[i] = hi;
            g_Bt1_lo[i] = lo;
        } else {
            int j = i - 256 * 256;
            int nn = j >> 8, k = j & 255;
            float w = (nn < 64) ? W_l2[(size_t)k * 64 + nn] : W_r2[(size_t)k * 64 + (nn - 64)];
            __nv_bfloat16 hi = __float2bfloat16(w);
            __nv_bfloat16 lo = __float2bfloat16(w - __bfloat162float(hi));
            g_Bt2_hi[j] = hi;
            g_Bt2_lo[j] = lo;
        }
    }
    grid_sync();

    int Lb = (n + G - 1) / G;
    int node = b * Lb + t;
    int deg = (t < Lb && node < n) ? g_deg[node] : 0;
    sh[t] = deg;
    __syncthreads();
    for (int s = 1; s < 256; s <<= 1) {
        int v = (t >= s) ? sh[t - s] : 0;
        __syncthreads();
        sh[t] += v;
        __syncthreads();
    }
    int ex = sh[t] - deg;
    if (t == 255) g_bsum[b] = sh[255];
    grid_sync();

    if (b == 0) {
        for (int i = t; i < G; i += 256) sb[i] = g_bsum[i];
        __syncthreads();
        for (int i = t; i < G; i += 256) {
            int acc = 0;
            for (int k = 0; k < i; k++) acc += sb[k];
            g_boff[i] = acc;
        }
    }
    grid_sync();

    int boff = g_boff[b];
    if (t < Lb && node < n) {
        g_off[node] = boff + ex;
        g_cur[node] = boff + ex;
    }
    if (b == G - 1 && t == 0) g_off[n] = g_boff[G - 1] + g_bsum[G - 1];
    grid_sync();

    for (int i = gid; i < n4; i += gstride) {
        int4 d = __ldg((const int4*)dst + i);
        int4 s = __ldg((const int4*)src + i);
        g_csr[atomicAdd(&g_cur[d.x], 1)] = s.x;
        g_csr[atomicAdd(&g_cur[d.y], 1)] = s.y;
        g_csr[atomicAdd(&g_cur[d.z], 1)] = s.z;
        g_csr[atomicAdd(&g_cur[d.w], 1)] = s.w;
    }
    if (gid < (e & 3)) {
        int j = n4 * 4 + gid;
        g_csr[atomicAdd(&g_cur[dst[j]], 1)] = src[j];
    }
}

// ---------------- layer-1 aggregation + x convert (fused, warp per node) -----
__global__ void agg128_kernel(const float* __restrict__ x) {
    int w = (blockIdx.x * blockDim.x + threadIdx.x) >> 5;
    int lane = threadIdx.x & 31;
    if (w >= N_NODES) return;
    int s = g_off[w], e = g_off[w + 1];
    float4 a0 = make_float4(0.f, 0.f, 0.f, 0.f), a1 = a0, a2 = a0, a3 = a0;
    int i = s;
    for (; i + 4 <= e; i += 4) {
        int s0 = g_csr[i], s1 = g_csr[i + 1], s2 = g_csr[i + 2], s3 = g_csr[i + 3];
        float4 v0 = __ldg(((const float4*)(x + (size_t)s0 * F_IN)) + lane);
        float4 v1 = __ldg(((const float4*)(x + (size_t)s1 * F_IN)) + lane);
        float4 v2 = __ldg(((const float4*)(x + (size_t)s2 * F_IN)) + lane);
        float4 v3 = __ldg(((const float4*)(x + (size_t)s3 * F_IN)) + lane);
        a0.x += v0.x; a0.y += v0.y; a0.z += v0.z; a0.w += v0.w;
        a1.x += v1.x; a1.y += v1.y; a1.z += v1.z; a1.w += v1.w;
        a2.x += v2.x; a2.y += v2.y; a2.z += v2.z; a2.w += v2.w;
        a3.x += v3.x; a3.y += v3.y; a3.z += v3.z; a3.w += v3.w;
    }
    for (; i < e; i++) {
        int sn = g_csr[i];
        float4 v = __ldg(((const float4*)(x + (size_t)sn * F_IN)) + lane);
        a0.x += v.x; a0.y += v.y; a0.z += v.z; a0.w += v.w;
    }
    float4 acc;
    acc.x = (a0.x + a1.x) + (a2.x + a3.x);
    acc.y = (a0.y + a1.y) + (a2.y + a3.y);
    acc.z = (a0.z + a1.z) + (a2.z + a3.z);
    acc.w = (a0.w + a1.w) + (a2.w + a3.w);
    float inv = (e > s) ? 1.0f / (float)(e - s) : 0.0f;
    acc.x *= inv; acc.y *= inv; acc.z *= inv; acc.w *= inv;
    uint2 hi, lo;
    split4(acc, hi, lo);
    *(uint2*)(g_A1hi + (size_t)w * 256 + lane * 4) = hi;
    *(uint2*)(g_A1lo + (size_t)w * 256 + lane * 4) = lo;
    float4 xv = __ldg(((const float4*)(x + (size_t)w * F_IN)) + lane);
    split4(xv, hi, lo);
    *(uint2*)(g_A1hi + (size_t)w * 256 + 128 + lane * 4) = hi;
    *(uint2*)(g_A1lo + (size_t)w * 256 + 128 + lane * 4) = lo;
}

// layer 2: mean of t fused with sigmoid epilogue; unroll-8 for MLP
__global__ void agg64_final_kernel(const float* __restrict__ b2, float* __restrict__ out) {
    int w = (blockIdx.x * blockDim.x + threadIdx.x) >> 5;
    int lane = threadIdx.x & 31;
    if (w >= N_NODES) return;
    int s = g_off[w], e = g_off[w + 1];
    float2 a0 = make_float2(0.f, 0.f), a1 = a0, a2 = a0, a3 = a0;
    float2 a4 = a0, a5 = a0, a6 = a0, a7 = a0;
    int i = s;
    for (; i + 8 <= e; i += 8) {
        int s0 = g_csr[i],     s1 = g_csr[i + 1], s2 = g_csr[i + 2], s3 = g_csr[i + 3];
        int s4 = g_csr[i + 4], s5 = g_csr[i + 5], s6 = g_csr[i + 6], s7 = g_csr[i + 7];
        float2 v0 = __ldg(((const float2*)(g_t + (size_t)s0 * F_OUT)) + lane);
        float2 v1 = __ldg(((const float2*)(g_t + (size_t)s1 * F_OUT)) + lane);
        float2 v2 = __ldg(((const float2*)(g_t + (size_t)s2 * F_OUT)) + lane);
        float2 v3 = __ldg(((const float2*)(g_t + (size_t)s3 * F_OUT)) + lane);
        float2 v4 = __ldg(((const float2*)(g_t + (size_t)s4 * F_OUT)) + lane);
        float2 v5 = __ldg(((const float2*)(g_t + (size_t)s5 * F_OUT)) + lane);
        float2 v6 = __ldg(((const float2*)(g_t + (size_t)s6 * F_OUT)) + lane);
        float2 v7 = __ldg(((const float2*)(g_t + (size_t)s7 * F_OUT)) + lane);
        a0.x += v0.x; a0.y += v0.y;
        a1.x += v1.x; a1.y += v1.y;
        a2.x += v2.x; a2.y += v2.y;
        a3.x += v3.x; a3.y += v3.y;
        a4.x += v4.x; a4.y += v4.y;
        a5.x += v5.x; a5.y += v5.y;
        a6.x += v6.x; a6.y += v6.y;
        a7.x += v7.x; a7.y += v7.y;
    }
    for (; i < e; i++) {
        int sn = g_csr[i];
        float2 v = __ldg(((const float2*)(g_t + (size_t)sn * F_OUT)) + lane);
        a0.x += v.x; a0.y += v.y;
    }
    float2 acc;
    acc.x = ((a0.x + a1.x) + (a2.x + a3.x)) + ((a4.x + a5.x) + (a6.x + a7.x));
    acc.y = ((a0.y + a1.y) + (a2.y + a3.y)) + ((a4.y + a5.y) + (a6.y + a7.y));
    float inv = (e > s) ? 1.0f / (float)(e - s) : 0.0f;
    float2 u = *(const float2*)(g_u + (size_t)w * F_OUT + lane * 2);
    float bx = __ldg(&b2[lane * 2]);
    float by = __ldg(&b2[lane * 2 + 1]);
    float vx = acc.x * inv + u.x + bx;
    float vy = acc.y * inv + u.y + by;
    float2 o;
    o.x = 1.f / (1.f + __expf(-vx));
    o.y = 1.f / (1.f + __expf(-vy));
    *(float2*)(out + (size_t)w * F_OUT + lane * 2) = o;
}

// ---------------- GEMM 1: 128x64 tiles, 3 CTAs/SM (best for MODE 1) ----------
// v = relu(A@Bt^T + bias); store bf16 hi/lo to oHi/oLo [M][256]
#define SM_BUF1    24576   // Ahi 8K | Alo 8K | Bhi 4K | Blo 4K
#define SMEM_GEMM1 73728   // 3 stages

__global__ __launch_bounds__(256, 3)
void gemm1_kernel(const __nv_bfloat16* __restrict__ Ahi, const __nv_bfloat16* __restrict__ Alo,
                  const __nv_bfloat16* __restrict__ Bhi, const __nv_bfloat16* __restrict__ Blo,
                  const float* __restrict__ bias,
                  __nv_bfloat16* __restrict__ oHi, __nv_bfloat16* __restrict__ oLo, int M)
{
    extern __shared__ __align__(128) char sm[];
    const uint32_t sb = smem_u32(sm);
    const int tid  = threadIdx.x;
    const int wid  = tid >> 5;
    const int lane = tid & 31;
    const int wm = (wid & 3) * 32;
    const int wn = (wid >> 2) * 32;
    const int rowBase = blockIdx.x * 128;
    const int colBase = blockIdx.y * 64;

    float acc[2][4][4];
#pragma unroll
    for (int a = 0; a < 2; a++)
#pragma unroll
        for (int b = 0; b < 4; b++)
#pragma unroll
            for (int c = 0; c < 4; c++) acc[a][b][c] = 0.f;

    auto issue = [&](int c, int buf) {
        uint32_t base = sb + buf * SM_BUF1;
#pragma unroll
        for (int i = tid; i < 512; i += 256) {
            int r = i >> 2, j = i & 3;
            uint32_t off = sw64((uint32_t)(r * 64 + j * 16));
            int arow = rowBase + r;
            int asz = (arow < M) ? 16 : 0;
            size_t aidx = (size_t)min(arow, M - 1) * 256 + c * 32 + j * 8;
            CP_ASYNC16(base + off,         (const char*)(Ahi + aidx), asz);
            CP_ASYNC16(base + 8192 + off,  (const char*)(Alo + aidx), asz);
        }
        {
            int r = tid >> 2, j = tid & 3;
            uint32_t off = sw64((uint32_t)(r * 64 + j * 16));
            size_t bidx = (size_t)(colBase + r) * 256 + c * 32 + j * 8;
            CP_ASYNC16(base + 16384 + off, (const char*)(Bhi + bidx), 16);
            CP_ASYNC16(base + 20480 + off, (const char*)(Blo + bidx), 16);
        }
        CP_COMMIT();
    };

    issue(0, 0);
    issue(1, 1);
#pragma unroll 1
    for (int c = 0; c < 8; c++) {
        if (c < 7) { CP_WAIT(1); } else { CP_WAIT(0); }
        __syncthreads();
        if (c < 6) issue(c + 2, (c + 2) % 3);
        uint32_t base = sb + (c % 3) * SM_BUF1;

        const int t = lane >> 3, rIn = lane & 7;
        const int rowAdd = rIn + (t & 1) * 8;
        const int kAdd = (t >> 1) * 16;
#pragma unroll
        for (int ks = 0; ks < 2; ks++) {
            int kB = ks * 32 + kAdd;
            uint32_t ah[2][4], al[2][4];
#pragma unroll
            for (int mt = 0; mt < 2; mt++) {
                uint32_t ad = base + sw64((uint32_t)((wm + mt * 16 + rowAdd) * 64 + kB));
                LDSM4(ah[mt], ad);
                LDSM4(al[mt], ad + 8192);
            }
#pragma unroll
            for (int n4 = 0; n4 < 2; n4++) {
                uint32_t bh[4], bl[4];
                uint32_t bd = base + 16384 + sw64((uint32_t)((wn + n4 * 16 + rowAdd) * 64 + kB));
                LDSM4(bh, bd);
                LDSM4(bl, bd + 4096);
#pragma unroll
                for (int hf = 0; hf < 2; hf++) {
                    int nt = n4 * 2 + hf;
                    MMA_BF16(acc[0][nt], ah[0], bh[hf], bh[hf + 2]);
                    MMA_BF16(acc[1][nt], ah[1], bh[hf], bh[hf + 2]);
                    MMA_BF16(acc[0][nt], ah[0], bl[hf], bl[hf + 2]);
                    MMA_BF16(acc[1][nt], ah[1], bl[hf], bl[hf + 2]);
                    MMA_BF16(acc[0][nt], al[0], bh[hf], bh[hf + 2]);
                    MMA_BF16(acc[1][nt], al[1], bh[hf], bh[hf + 2]);
                }
            }
        }
    }
    __syncthreads();

    float* sep = (float*)sm;   // 128 x 68 fp32
    const int g = lane >> 2, cp2 = (lane & 3) * 2;
#pragma unroll
    for (int mt = 0; mt < 2; mt++)
#pragma unroll
        for (int nt = 0; nt < 4; nt++) {
            int r0 = wm + mt * 16 + g;
            int cc = wn + nt * 8 + cp2;
            float bA = __ldg(&bias[colBase + cc]);
            float bB = __ldg(&bias[colBase + cc + 1]);
            sep[r0 * 68 + cc]           = fmaxf(acc[mt][nt][0] + bA, 0.f);
            sep[r0 * 68 + cc + 1]       = fmaxf(acc[mt][nt][1] + bB, 0.f);
            sep[(r0 + 8) * 68 + cc]     = fmaxf(acc[mt][nt][2] + bA, 0.f);
            sep[(r0 + 8) * 68 + cc + 1] = fmaxf(acc[mt][nt][3] + bB, 0.f);
        }
    __syncthreads();
#pragma unroll 1
    for (int i = tid; i < 128 * 16; i += 256) {
        int r = i >> 4, c4 = (i & 15) * 4;
        int row = rowBase + r;
        if (row < M) {
            float4 v = *(const float4*)&sep[r * 68 + c4];
            uint2 hi, lo;
            split4(v, hi, lo);
            size_t o = (size_t)row * 256 + colBase + c4;
            *(uint2*)(oHi + o) = hi;
            *(uint2*)(oLo + o) = lo;
        }
    }
}

// ---------------- GEMM 2: 128x128 tile, 8 warps, 2 CTAs/SM (best for MODE 2) -
// [t|u] = A@Bt2^T; cols 0:64 -> t fp32, 64:128 -> u fp32
#define SM_BUF2    32768   // Ahi 8K | Alo 8K | Bhi 8K | Blo 8K
#define SMEM_GEMM2 98304   // 3 stages

__global__ __launch_bounds__(256, 2)
void gemm2_kernel(const __nv_bfloat16* __restrict__ Ahi, const __nv_bfloat16* __restrict__ Alo,
                  const __nv_bfloat16* __restrict__ Bhi, const __nv_bfloat16* __restrict__ Blo,
                  float* __restrict__ o0, float* __restrict__ o1, int M)
{
    extern __shared__ __align__(128) char sm[];
    const uint32_t sb = smem_u32(sm);
    const int tid  = threadIdx.x;
    const int wid  = tid >> 5;
    const int lane = tid & 31;
    const int wm = (wid & 3) * 32;    // 4 warps along M
    const int wn = (wid >> 2) * 64;   // 2 warps along N
    const int rowBase = blockIdx.x * 128;

    float acc[2][8][4];
#pragma unroll
    for (int a = 0; a < 2; a++)
#pragma unroll
        for (int b = 0; b < 8; b++)
#pragma unroll
            for (int c = 0; c < 4; c++) acc[a][b][c] = 0.f;

    auto issue = [&](int c, int buf) {
        uint32_t base = sb + buf * SM_BUF2;
#pragma unroll
        for (int i = tid; i < 512; i += 256) {
            int r = i >> 2, j = i & 3;
            uint32_t off = sw64((uint32_t)(r * 64 + j * 16));
            int arow = rowBase + r;
            int asz = (arow < M) ? 16 : 0;
            size_t aidx = (size_t)min(arow, M - 1) * 256 + c * 32 + j * 8;
            CP_ASYNC16(base + off,         (const char*)(Ahi + aidx), asz);
            CP_ASYNC16(base + 8192 + off,  (const char*)(Alo + aidx), asz);
            size_t bidx = (size_t)r * 256 + c * 32 + j * 8;
            CP_ASYNC16(base + 16384 + off, (const char*)(Bhi + bidx), 16);
            CP_ASYNC16(base + 24576 + off, (const char*)(Blo + bidx), 16);
        }
        CP_COMMIT();
    };

    issue(0, 0);
    issue(1, 1);
#pragma unroll 1
    for (int c = 0; c < 8; c++) {
        if (c < 7) { CP_WAIT(1); } else { CP_WAIT(0); }
        __syncthreads();
        if (c < 6) issue(c + 2, (c + 2) % 3);
        uint32_t base = sb + (c % 3) * SM_BUF2;

        const int t = lane >> 3, rIn = lane & 7;
        const int rowAdd = rIn + (t & 1) * 8;
        const int kAdd = (t >> 1) * 16;
#pragma unroll
        for (int ks = 0; ks < 2; ks++) {
            int kB = ks * 32 + kAdd;
            uint32_t ah[2][4], al[2][4];
#pragma unroll
            for (int mt = 0; mt < 2; mt++) {
                uint32_t ad = base + sw64((uint32_t)((wm + mt * 16 + rowAdd) * 64 + kB));
                LDSM4(ah[mt], ad);
                LDSM4(al[mt], ad + 8192);
            }
#pragma unroll
            for (int n4 = 0; n4 < 4; n4++) {
                uint32_t bh[4], bl[4];
                uint32_t bd = base + 16384 + sw64((uint32_t)((wn + n4 * 16 + rowAdd) * 64 + kB));
                LDSM4(bh, bd);
                LDSM4(bl, bd + 8192);
#pragma unroll
                for (int hf = 0; hf < 2; hf++) {
                    int nt = n4 * 2 + hf;
                    MMA_BF16(acc[0][nt], ah[0], bh[hf], bh[hf + 2]);
                    MMA_BF16(acc[1][nt], ah[1], bh[hf], bh[hf + 2]);
                    MMA_BF16(acc[0][nt], ah[0], bl[hf], bl[hf + 2]);
                    MMA_BF16(acc[1][nt], ah[1], bl[hf], bl[hf + 2]);
                    MMA_BF16(acc[0][nt], al[0], bh[hf], bh[hf + 2]);
                    MMA_BF16(acc[1][nt], al[1], bh[hf], bh[hf + 2]);
                }
            }
        }
    }
    __syncthreads();

    float* sep = (float*)sm;   // 128 x 68 fp32 per half
    const int g = lane >> 2, cp2 = (lane & 3) * 2;
#pragma unroll 1
    for (int half = 0; half < 2; half++) {
        if (wn == half * 64) {
#pragma unroll
            for (int mt = 0; mt < 2; mt++)
#pragma unroll
                for (int nt = 0; nt < 8; nt++) {
                    int r0 = wm + mt * 16 + g;
                    int cc = nt * 8 + cp2;
                    sep[r0 * 68 + cc]           = acc[mt][nt][0];
                    sep[r0 * 68 + cc + 1]       = acc[mt][nt][1];
                    sep[(r0 + 8) * 68 + cc]     = acc[mt][nt][2];
                    sep[(r0 + 8) * 68 + cc + 1] = acc[mt][nt][3];
                }
        }
        __syncthreads();
#pragma unroll 1
        for (int i = tid; i < 128 * 16; i += 256) {
            int r = i >> 4, c4 = (i & 15) * 4;
            int row = rowBase + r;
            if (row < M) {
                float4 v = *(const float4*)&sep[r * 68 + c4];
                float* dstp = half ? o1 : o0;
                *(float4*)(dstp + (size_t)row * 64 + c4) = v;
            }
        }
        __syncthreads();
    }
}

// ---------------- launch -----------------------------------------------------
extern "C" void kernel_launch(void* const* d_in, const int* in_sizes, int n_in,
                              void* d_out, int out_size)
{
    const float* x    = (const float*)d_in[0];
    const int*   ei   = (const int*)  d_in[1];
    const float* W_l1 = (const float*)d_in[2];
    const float* W_r1 = (const float*)d_in[3];
    const float* b1   = (const float*)d_in[4];
    const float* W_l2 = (const float*)d_in[5];
    const float* W_r2 = (const float*)d_in[6];
    const float* b2   = (const float*)d_in[7];
    float*       out  = (float*)d_out;

    int n = in_sizes[0] / F_IN;
    int e = in_sizes[1] / 2;
    const int* srcp = ei;
    const int* dstp = ei + e;

    __nv_bfloat16 *a1h, *a1l, *a2h, *a2l, *bt1h, *bt1l, *bt2h, *bt2l;
    float *t_p, *u_p;
    cudaGetSymbolAddress((void**)&a1h,  g_A1hi);
    cudaGetSymbolAddress((void**)&a1l,  g_A1lo);
    cudaGetSymbolAddress((void**)&a2h,  g_A2hi);
    cudaGetSymbolAddress((void**)&a2l,  g_A2lo);
    cudaGetSymbolAddress((void**)&bt1h, g_Bt1_hi);
    cudaGetSymbolAddress((void**)&bt1l, g_Bt1_lo);
    cudaGetSymbolAddress((void**)&bt2h, g_Bt2_hi);
    cudaGetSymbolAddress((void**)&bt2l, g_Bt2_lo);
    cudaGetSymbolAddress((void**)&t_p,  g_t);
    cudaGetSymbolAddress((void**)&u_p,  g_u);

    cudaFuncSetAttribute(gemm1_kernel, cudaFuncAttributeMaxDynamicSharedMemorySize, SMEM_GEMM1);
    cudaFuncSetAttribute(gemm2_kernel, cudaFuncAttributeMaxDynamicSharedMemorySize, SMEM_GEMM2);

    int mtiles = (n + 127) / 128;

    // CSR build + weight prep (fused persistent kernel)
    csr_coop_kernel<<<GSYNC_BLOCKS, 256>>>(srcp, dstp, W_l1, W_r1, W_l2, W_r2, e, n); // 0
    // layer-1 aggregation + x convert
    agg128_kernel<<<(n * 32 + 255) / 256, 256>>>(x);                     // 1
    // h = relu([agg1|x] @ [W_l1;W_r1] + b1) -> A2 hi/lo
    gemm1_kernel<<<dim3(mtiles, 4), 256, SMEM_GEMM1>>>(a1h, a1l, bt1h, bt1l, b1,
                                                       a2h, a2l, n);     // 2
    // [t|u] = h @ [W_l2|W_r2]
    gemm2_kernel<<<mtiles, 256, SMEM_GEMM2>>>(a2h, a2l, bt2h, bt2l, t_p, u_p, n); // 3 (profiled)
    // layer-2 aggregation of t + sigmoid epilogue (unroll-8)
    agg64_final_kernel<<<(n * 32 + 255) / 256, 256>>>(b2, out);          // 4
}

// round 15
// speedup vs baseline: 1.0247x; 1.0060x over previous
#include <cuda_runtime.h>
#include <cuda_bf16.h>
#include <math.h>
#include <stdint.h>

// Problem constants
#define N_NODES 50000
#define N_EDGES 800000
#define F_IN    128
#define F_HID   256
#define F_OUT   64

#define GSYNC_BLOCKS 296   // 2 per SM, guaranteed co-resident

// ---------------- scratch (static __device__; no allocation) -----------------
__device__ int      g_deg[N_NODES];
__device__ int      g_off[N_NODES + 1];
__device__ int      g_cur[N_NODES];
__device__ int      g_csr[N_EDGES];
__device__ int      g_bsum[GSYNC_BLOCKS];
__device__ int      g_boff[GSYNC_BLOCKS];
__device__ unsigned g_barc;               // monotonic grid-barrier counter
// Layer-1 A = [agg1 | x] pre-split to bf16 hi/lo, [M][256]
__device__ __nv_bfloat16 g_A1hi[(size_t)N_NODES * 256];
__device__ __nv_bfloat16 g_A1lo[(size_t)N_NODES * 256];
// Layer-2 A = h (relu hidden) pre-split to bf16 hi/lo, [M][256]
__device__ __nv_bfloat16 g_A2hi[(size_t)N_NODES * 256];
__device__ __nv_bfloat16 g_A2lo[(size_t)N_NODES * 256];
__device__ float g_t[(size_t)N_NODES * F_OUT];   // h @ W_l2
__device__ float g_u[(size_t)N_NODES * F_OUT];   // h @ W_r2
// pre-split / transposed / stacked weights (bf16 hi+lo), [N][K] k-contiguous
__device__ __nv_bfloat16 g_Bt1_hi[256 * 256];
__device__ __nv_bfloat16 g_Bt1_lo[256 * 256];
__device__ __nv_bfloat16 g_Bt2_hi[128 * 256];
__device__ __nv_bfloat16 g_Bt2_lo[128 * 256];

// ---------------- helpers ----------------------------------------------------
__device__ __forceinline__ uint32_t smem_u32(const void* p) {
    uint32_t a;
    asm("{ .reg .u64 t; cvta.to.shared.u64 t, %1; cvt.u32.u64 %0, t; }" : "=r"(a) : "l"(p));
    return a;
}
__device__ __forceinline__ uint32_t sw64(uint32_t off) { return off ^ ((off >> 3) & 0x30); }

__device__ __forceinline__ uint32_t pack2(__nv_bfloat16 a, __nv_bfloat16 b) {
    return (uint32_t)__bfloat16_as_ushort(a) | ((uint32_t)__bfloat16_as_ushort(b) << 16);
}
__device__ __forceinline__ void split4(float4 v, uint2& hi, uint2& lo) {
    __nv_bfloat16 h0 = __float2bfloat16(v.x), h1 = __float2bfloat16(v.y);
    __nv_bfloat16 h2 = __float2bfloat16(v.z), h3 = __float2bfloat16(v.w);
    __nv_bfloat16 l0 = __float2bfloat16(v.x - __bfloat162float(h0));
    __nv_bfloat16 l1 = __float2bfloat16(v.y - __bfloat162float(h1));
    __nv_bfloat16 l2 = __float2bfloat16(v.z - __bfloat162float(h2));
    __nv_bfloat16 l3 = __float2bfloat16(v.w - __bfloat162float(h3));
    hi.x = pack2(h0, h1); hi.y = pack2(h2, h3);
    lo.x = pack2(l0, l1); lo.y = pack2(l2, l3);
}

#define CP_ASYNC16(dst, src, sz) \
    asm volatile("cp.async.cg.shared.global [%0], [%1], 16, %2;" \
                 :: "r"(dst), "l"(src), "r"(sz) : "memory")
#define CP_COMMIT() asm volatile("cp.async.commit_group;" ::: "memory")
#define CP_WAIT(n)  asm volatile("cp.async.wait_group %0;" :: "n"(n) : "memory")

#define LDSM4(r, addr) \
    asm volatile("ldmatrix.sync.aligned.m8n8.x4.shared.b16 {%0,%1,%2,%3}, [%4];" \
                 : "=r"((r)[0]), "=r"((r)[1]), "=r"((r)[2]), "=r"((r)[3]) : "r"(addr))

#define MMA_BF16(d, a, b0, b1) \
    asm volatile("mma.sync.aligned.m16n8k16.row.col.f32.bf16.bf16.f32 " \
                 "{%0,%1,%2,%3}, {%4,%5,%6,%7}, {%8,%9}, {%0,%1,%2,%3};" \
                 : "+f"((d)[0]), "+f"((d)[1]), "+f"((d)[2]), "+f"((d)[3]) \
                 : "r"((a)[0]), "r"((a)[1]), "r"((a)[2]), "r"((a)[3]), "r"(b0), "r"(b1))

// Monotonic-counter grid barrier (counter never reset; wrap unreachable).
__device__ __forceinline__ void grid_sync() {
    __syncthreads();
    if (threadIdx.x == 0) {
        __threadfence();
        unsigned arrive = atomicAdd(&g_barc, 1) + 1;
        unsigned target = ((arrive + GSYNC_BLOCKS - 1) / GSYNC_BLOCKS) * GSYNC_BLOCKS;
        while (atomicAdd(&g_barc, 0) < target) __nanosleep(64);
        __threadfence();
    }
    __syncthreads();
}

// ---------------- CSR build + weight prep: one persistent kernel -------------
__global__ __launch_bounds__(256)
void csr_coop_kernel(const int* __restrict__ src, const int* __restrict__ dst,
                     const float* __restrict__ W_l1, const float* __restrict__ W_r1,
                     const float* __restrict__ W_l2, const float* __restrict__ W_r2,
                     int e, int n)
{
    const int G = GSYNC_BLOCKS;
    const int b = blockIdx.x, t = threadIdx.x;
    const int gid = b * 256 + t, gstride = G * 256;
    __shared__ int sh[256];
    __shared__ int sb[GSYNC_BLOCKS];

    for (int i = gid; i < n; i += gstride) g_deg[i] = 0;
    grid_sync();

    // phase 1: count + weight prep (independent work, overlapped)
    int n4 = e >> 2;
    for (int i = gid; i < n4; i += gstride) {
        int4 d = __ldg((const int4*)dst + i);
        atomicAdd(&g_deg[d.x], 1);
        atomicAdd(&g_deg[d.y], 1);
        atomicAdd(&g_deg[d.z], 1);
        atomicAdd(&g_deg[d.w], 1);
    }
    if (gid < (e & 3)) atomicAdd(&g_deg[dst[n4 * 4 + gid]], 1);
    for (int i = gid; i < 256 * 256 + 128 * 256; i += gstride) {
        if (i < 256 * 256) {
            int nn = i >> 8, k = i & 255;
            float w = (k < 128) ? W_l1[(size_t)k * 256 + nn] : W_r1[(size_t)(k - 128) * 256 + nn];
            __nv_bfloat16 hi = __float2bfloat16(w);
            __nv_bfloat16 lo = __float2bfloat16(w - __bfloat162float(hi));
            g_Bt1_hi[i] = hi;
            g_Bt1_lo[i] = lo;
        } else {
            int j = i - 256 * 256;
            int nn = j >> 8, k = j & 255;
            float w = (nn < 64) ? W_l2[(size_t)k * 64 + nn] : W_r2[(size_t)k * 64 + (nn - 64)];
            __nv_bfloat16 hi = __float2bfloat16(w);
            __nv_bfloat16 lo = __float2bfloat16(w - __bfloat162float(hi));
            g_Bt2_hi[j] = hi;
            g_Bt2_lo[j] = lo;
        }
    }
    grid_sync();

    int Lb = (n + G - 1) / G;
    int node = b * Lb + t;
    int deg = (t < Lb && node < n) ? g_deg[node] : 0;
    sh[t] = deg;
    __syncthreads();
    for (int s = 1; s < 256; s <<= 1) {
        int v = (t >= s) ? sh[t - s] : 0;
        __syncthreads();
        sh[t] += v;
        __syncthreads();
    }
    int ex = sh[t] - deg;
    if (t == 255) g_bsum[b] = sh[255];
    grid_sync();

    if (b == 0) {
        for (int i = t; i < G; i += 256) sb[i] = g_bsum[i];
        __syncthreads();
        for (int i = t; i < G; i += 256) {
            int acc = 0;
            for (int k = 0; k < i; k++) acc += sb[k];
            g_boff[i] = acc;
        }
    }
    grid_sync();

    int boff = g_boff[b];
    if (t < Lb && node < n) {
        g_off[node] = boff + ex;
        g_cur[node] = boff + ex;
    }
    if (b == G - 1 && t == 0) g_off[n] = g_boff[G - 1] + g_bsum[G - 1];
    grid_sync();

    for (int i = gid; i < n4; i += gstride) {
        int4 d = __ldg((const int4*)dst + i);
        int4 s = __ldg((const int4*)src + i);
        g_csr[atomicAdd(&g_cur[d.x], 1)] = s.x;
        g_csr[atomicAdd(&g_cur[d.y], 1)] = s.y;
        g_csr[atomicAdd(&g_cur[d.z], 1)] = s.z;
        g_csr[atomicAdd(&g_cur[d.w], 1)] = s.w;
    }
    if (gid < (e & 3)) {
        int j = n4 * 4 + gid;
        g_csr[atomicAdd(&g_cur[dst[j]], 1)] = src[j];
    }
}

// ---------------- layer-1 aggregation + x convert (fused, warp per node) -----
__global__ void agg128_kernel(const float* __restrict__ x) {
    int w = (blockIdx.x * blockDim.x + threadIdx.x) >> 5;
    int lane = threadIdx.x & 31;
    if (w >= N_NODES) return;
    int s = g_off[w], e = g_off[w + 1];
    float4 a0 = make_float4(0.f, 0.f, 0.f, 0.f), a1 = a0, a2 = a0, a3 = a0;
    int i = s;
    for (; i + 4 <= e; i += 4) {
        int s0 = g_csr[i], s1 = g_csr[i + 1], s2 = g_csr[i + 2], s3 = g_csr[i + 3];
        float4 v0 = __ldg(((const float4*)(x + (size_t)s0 * F_IN)) + lane);
        float4 v1 = __ldg(((const float4*)(x + (size_t)s1 * F_IN)) + lane);
        float4 v2 = __ldg(((const float4*)(x + (size_t)s2 * F_IN)) + lane);
        float4 v3 = __ldg(((const float4*)(x + (size_t)s3 * F_IN)) + lane);
        a0.x += v0.x; a0.y += v0.y; a0.z += v0.z; a0.w += v0.w;
        a1.x += v1.x; a1.y += v1.y; a1.z += v1.z; a1.w += v1.w;
        a2.x += v2.x; a2.y += v2.y; a2.z += v2.z; a2.w += v2.w;
        a3.x += v3.x; a3.y += v3.y; a3.z += v3.z; a3.w += v3.w;
    }
    for (; i < e; i++) {
        int sn = g_csr[i];
        float4 v = __ldg(((const float4*)(x + (size_t)sn * F_IN)) + lane);
        a0.x += v.x; a0.y += v.y; a0.z += v.z; a0.w += v.w;
    }
    float4 acc;
    acc.x = (a0.x + a1.x) + (a2.x + a3.x);
    acc.y = (a0.y + a1.y) + (a2.y + a3.y);
    acc.z = (a0.z + a1.z) + (a2.z + a3.z);
    acc.w = (a0.w + a1.w) + (a2.w + a3.w);
    float inv = (e > s) ? 1.0f / (float)(e - s) : 0.0f;
    acc.x *= inv; acc.y *= inv; acc.z *= inv; acc.w *= inv;
    uint2 hi, lo;
    split4(acc, hi, lo);
    *(uint2*)(g_A1hi + (size_t)w * 256 + lane * 4) = hi;
    *(uint2*)(g_A1lo + (size_t)w * 256 + lane * 4) = lo;
    float4 xv = __ldg(((const float4*)(x + (size_t)w * F_IN)) + lane);
    split4(xv, hi, lo);
    *(uint2*)(g_A1hi + (size_t)w * 256 + 128 + lane * 4) = hi;
    *(uint2*)(g_A1lo + (size_t)w * 256 + 128 + lane * 4) = lo;
}

// layer 2: mean of t fused with sigmoid epilogue (unroll-4, measured best)
__global__ void agg64_final_kernel(const float* __restrict__ b2, float* __restrict__ out) {
    int w = (blockIdx.x * blockDim.x + threadIdx.x) >> 5;
    int lane = threadIdx.x & 31;
    if (w >= N_NODES) return;
    int s = g_off[w], e = g_off[w + 1];
    float2 a0 = make_float2(0.f, 0.f), a1 = a0, a2 = a0, a3 = a0;
    int i = s;
    for (; i + 4 <= e; i += 4) {
        int s0 = g_csr[i], s1 = g_csr[i + 1], s2 = g_csr[i + 2], s3 = g_csr[i + 3];
        float2 v0 = __ldg(((const float2*)(g_t + (size_t)s0 * F_OUT)) + lane);
        float2 v1 = __ldg(((const float2*)(g_t + (size_t)s1 * F_OUT)) + lane);
        float2 v2 = __ldg(((const float2*)(g_t + (size_t)s2 * F_OUT)) + lane);
        float2 v3 = __ldg(((const float2*)(g_t + (size_t)s3 * F_OUT)) + lane);
        a0.x += v0.x; a0.y += v0.y;
        a1.x += v1.x; a1.y += v1.y;
        a2.x += v2.x; a2.y += v2.y;
        a3.x += v3.x; a3.y += v3.y;
    }
    for (; i < e; i++) {
        int sn = g_csr[i];
        float2 v = __ldg(((const float2*)(g_t + (size_t)sn * F_OUT)) + lane);
        a0.x += v.x; a0.y += v.y;
    }
    float2 acc;
    acc.x = (a0.x + a1.x) + (a2.x + a3.x);
    acc.y = (a0.y + a1.y) + (a2.y + a3.y);
    float inv = (e > s) ? 1.0f / (float)(e - s) : 0.0f;
    float2 u = *(const float2*)(g_u + (size_t)w * F_OUT + lane * 2);
    float bx = __ldg(&b2[lane * 2]);
    float by = __ldg(&b2[lane * 2 + 1]);
    float vx = acc.x * inv + u.x + bx;
    float vy = acc.y * inv + u.y + by;
    float2 o;
    o.x = 1.f / (1.f + __expf(-vx));
    o.y = 1.f / (1.f + __expf(-vy));
    *(float2*)(out + (size_t)w * F_OUT + lane * 2) = o;
}

// ---------------- GEMM 1: 128x64 tiles, 3 CTAs/SM (measured best, MODE 1) ----
// v = relu(A@Bt^T + bias); store bf16 hi/lo to oHi/oLo [M][256]
#define SM_BUF1    24576   // Ahi 8K | Alo 8K | Bhi 4K | Blo 4K
#define SMEM_GEMM1 73728   // 3 stages

__global__ __launch_bounds__(256, 3)
void gemm1_kernel(const __nv_bfloat16* __restrict__ Ahi, const __nv_bfloat16* __restrict__ Alo,
                  const __nv_bfloat16* __restrict__ Bhi, const __nv_bfloat16* __restrict__ Blo,
                  const float* __restrict__ bias,
                  __nv_bfloat16* __restrict__ oHi, __nv_bfloat16* __restrict__ oLo, int M)
{
    extern __shared__ __align__(128) char sm[];
    const uint32_t sb = smem_u32(sm);
    const int tid  = threadIdx.x;
    const int wid  = tid >> 5;
    const int lane = tid & 31;
    const int wm = (wid & 3) * 32;
    const int wn = (wid >> 2) * 32;
    const int rowBase = blockIdx.x * 128;
    const int colBase = blockIdx.y * 64;

    float acc[2][4][4];
#pragma unroll
    for (int a = 0; a < 2; a++)
#pragma unroll
        for (int b = 0; b < 4; b++)
#pragma unroll
            for (int c = 0; c < 4; c++) acc[a][b][c] = 0.f;

    auto issue = [&](int c, int buf) {
        uint32_t base = sb + buf * SM_BUF1;
#pragma unroll
        for (int i = tid; i < 512; i += 256) {
            int r = i >> 2, j = i & 3;
            uint32_t off = sw64((uint32_t)(r * 64 + j * 16));
            int arow = rowBase + r;
            int asz = (arow < M) ? 16 : 0;
            size_t aidx = (size_t)min(arow, M - 1) * 256 + c * 32 + j * 8;
            CP_ASYNC16(base + off,         (const char*)(Ahi + aidx), asz);
            CP_ASYNC16(base + 8192 + off,  (const char*)(Alo + aidx), asz);
        }
        {
            int r = tid >> 2, j = tid & 3;
            uint32_t off = sw64((uint32_t)(r * 64 + j * 16));
            size_t bidx = (size_t)(colBase + r) * 256 + c * 32 + j * 8;
            CP_ASYNC16(base + 16384 + off, (const char*)(Bhi + bidx), 16);
            CP_ASYNC16(base + 20480 + off, (const char*)(Blo + bidx), 16);
        }
        CP_COMMIT();
    };

    issue(0, 0);
    issue(1, 1);
#pragma unroll 1
    for (int c = 0; c < 8; c++) {
        if (c < 7) { CP_WAIT(1); } else { CP_WAIT(0); }
        __syncthreads();
        if (c < 6) issue(c + 2, (c + 2) % 3);
        uint32_t base = sb + (c % 3) * SM_BUF1;

        const int t = lane >> 3, rIn = lane & 7;
        const int rowAdd = rIn + (t & 1) * 8;
        const int kAdd = (t >> 1) * 16;
#pragma unroll
        for (int ks = 0; ks < 2; ks++) {
            int kB = ks * 32 + kAdd;
            uint32_t ah[2][4], al[2][4];
#pragma unroll
            for (int mt = 0; mt < 2; mt++) {
                uint32_t ad = base + sw64((uint32_t)((wm + mt * 16 + rowAdd) * 64 + kB));
                LDSM4(ah[mt], ad);
                LDSM4(al[mt], ad + 8192);
            }
#pragma unroll
            for (int n4 = 0; n4 < 2; n4++) {
                uint32_t bh[4], bl[4];
                uint32_t bd = base + 16384 + sw64((uint32_t)((wn + n4 * 16 + rowAdd) * 64 + kB));
                LDSM4(bh, bd);
                LDSM4(bl, bd + 4096);
#pragma unroll
                for (int hf = 0; hf < 2; hf++) {
                    int nt = n4 * 2 + hf;
                    MMA_BF16(acc[0][nt], ah[0], bh[hf], bh[hf + 2]);
                    MMA_BF16(acc[1][nt], ah[1], bh[hf], bh[hf + 2]);
                    MMA_BF16(acc[0][nt], ah[0], bl[hf], bl[hf + 2]);
                    MMA_BF16(acc[1][nt], ah[1], bl[hf], bl[hf + 2]);
                    MMA_BF16(acc[0][nt], al[0], bh[hf], bh[hf + 2]);
                    MMA_BF16(acc[1][nt], al[1], bh[hf], bh[hf + 2]);
                }
            }
        }
    }
    __syncthreads();

    float* sep = (float*)sm;   // 128 x 68 fp32
    const int g = lane >> 2, cp2 = (lane & 3) * 2;
#pragma unroll
    for (int mt = 0; mt < 2; mt++)
#pragma unroll
        for (int nt = 0; nt < 4; nt++) {
            int r0 = wm + mt * 16 + g;
            int cc = wn + nt * 8 + cp2;
            float bA = __ldg(&bias[colBase + cc]);
            float bB = __ldg(&bias[colBase + cc + 1]);
            sep[r0 * 68 + cc]           = fmaxf(acc[mt][nt][0] + bA, 0.f);
            sep[r0 * 68 + cc + 1]       = fmaxf(acc[mt][nt][1] + bB, 0.f);
            sep[(r0 + 8) * 68 + cc]     = fmaxf(acc[mt][nt][2] + bA, 0.f);
            sep[(r0 + 8) * 68 + cc + 1] = fmaxf(acc[mt][nt][3] + bB, 0.f);
        }
    __syncthreads();
#pragma unroll 1
    for (int i = tid; i < 128 * 16; i += 256) {
        int r = i >> 4, c4 = (i & 15) * 4;
        int row = rowBase + r;
        if (row < M) {
            float4 v = *(const float4*)&sep[r * 68 + c4];
            uint2 hi, lo;
            split4(v, hi, lo);
            size_t o = (size_t)row * 256 + colBase + c4;
            *(uint2*)(oHi + o) = hi;
            *(uint2*)(oLo + o) = lo;
        }
    }
}

// ---------------- GEMM 2: 128x128 tile, 2 CTAs/SM (measured best, MODE 2) ----
// [t|u] = A@Bt2^T; cols 0:64 -> t fp32, 64:128 -> u fp32
#define SM_BUF2    32768   // Ahi 8K | Alo 8K | Bhi 8K | Blo 8K
#define SMEM_GEMM2 98304   // 3 stages

__global__ __launch_bounds__(256, 2)
void gemm2_kernel(const __nv_bfloat16* __restrict__ Ahi, const __nv_bfloat16* __restrict__ Alo,
                  const __nv_bfloat16* __restrict__ Bhi, const __nv_bfloat16* __restrict__ Blo,
                  float* __restrict__ o0, float* __restrict__ o1, int M)
{
    extern __shared__ __align__(128) char sm[];
    const uint32_t sb = smem_u32(sm);
    const int tid  = threadIdx.x;
    const int wid  = tid >> 5;
    const int lane = tid & 31;
    const int wm = (wid & 3) * 32;    // 4 warps along M
    const int wn = (wid >> 2) * 64;   // 2 warps along N
    const int rowBase = blockIdx.x * 128;

    float acc[2][8][4];
#pragma unroll
    for (int a = 0; a < 2; a++)
#pragma unroll
        for (int b = 0; b < 8; b++)
#pragma unroll
            for (int c = 0; c < 4; c++) acc[a][b][c] = 0.f;

    auto issue = [&](int c, int buf) {
        uint32_t base = sb + buf * SM_BUF2;
#pragma unroll
        for (int i = tid; i < 512; i += 256) {
            int r = i >> 2, j = i & 3;
            uint32_t off = sw64((uint32_t)(r * 64 + j * 16));
            int arow = rowBase + r;
            int asz = (arow < M) ? 16 : 0;
            size_t aidx = (size_t)min(arow, M - 1) * 256 + c * 32 + j * 8;
            CP_ASYNC16(base + off,         (const char*)(Ahi + aidx), asz);
            CP_ASYNC16(base + 8192 + off,  (const char*)(Alo + aidx), asz);
            size_t bidx = (size_t)r * 256 + c * 32 + j * 8;
            CP_ASYNC16(base + 16384 + off, (const char*)(Bhi + bidx), 16);
            CP_ASYNC16(base + 24576 + off, (const char*)(Blo + bidx), 16);
        }
        CP_COMMIT();
    };

    issue(0, 0);
    issue(1, 1);
#pragma unroll 1
    for (int c = 0; c < 8; c++) {
        if (c < 7) { CP_WAIT(1); } else { CP_WAIT(0); }
        __syncthreads();
        if (c < 6) issue(c + 2, (c + 2) % 3);
        uint32_t base = sb + (c % 3) * SM_BUF2;

        const int t = lane >> 3, rIn = lane & 7;
        const int rowAdd = rIn + (t & 1) * 8;
        const int kAdd = (t >> 1) * 16;
#pragma unroll
        for (int ks = 0; ks < 2; ks++) {
            int kB = ks * 32 + kAdd;
            uint32_t ah[2][4], al[2][4];
#pragma unroll
            for (int mt = 0; mt < 2; mt++) {
                uint32_t ad = base + sw64((uint32_t)((wm + mt * 16 + rowAdd) * 64 + kB));
                LDSM4(ah[mt], ad);
                LDSM4(al[mt], ad + 8192);
            }
#pragma unroll
            for (int n4 = 0; n4 < 4; n4++) {
                uint32_t bh[4], bl[4];
                uint32_t bd = base + 16384 + sw64((uint32_t)((wn + n4 * 16 + rowAdd) * 64 + kB));
                LDSM4(bh, bd);
                LDSM4(bl, bd + 8192);
#pragma unroll
                for (int hf = 0; hf < 2; hf++) {
                    int nt = n4 * 2 + hf;
                    MMA_BF16(acc[0][nt], ah[0], bh[hf], bh[hf + 2]);
                    MMA_BF16(acc[1][nt], ah[1], bh[hf], bh[hf + 2]);
                    MMA_BF16(acc[0][nt], ah[0], bl[hf], bl[hf + 2]);
                    MMA_BF16(acc[1][nt], ah[1], bl[hf], bl[hf + 2]);
                    MMA_BF16(acc[0][nt], al[0], bh[hf], bh[hf + 2]);
                    MMA_BF16(acc[1][nt], al[1], bh[hf], bh[hf + 2]);
                }
            }
        }
    }
    __syncthreads();

    float* sep = (float*)sm;   // 128 x 68 fp32 per half
    const int g = lane >> 2, cp2 = (lane & 3) * 2;
#pragma unroll 1
    for (int half = 0; half < 2; half++) {
        if (wn == half * 64) {
#pragma unroll
            for (int mt = 0; mt < 2; mt++)
#pragma unroll
                for (int nt = 0; nt < 8; nt++) {
                    int r0 = wm + mt * 16 + g;
                    int cc = nt * 8 + cp2;
                    sep[r0 * 68 + cc]           = acc[mt][nt][0];
                    sep[r0 * 68 + cc + 1]       = acc[mt][nt][1];
                    sep[(r0 + 8) * 68 + cc]     = acc[mt][nt][2];
                    sep[(r0 + 8) * 68 + cc + 1] = acc[mt][nt][3];
                }
        }
        __syncthreads();
#pragma unroll 1
        for (int i = tid; i < 128 * 16; i += 256) {
            int r = i >> 4, c4 = (i & 15) * 4;
            int row = rowBase + r;
            if (row < M) {
                float4 v = *(const float4*)&sep[r * 68 + c4];
                float* dstp = half ? o1 : o0;
                *(float4*)(dstp + (size_t)row * 64 + c4) = v;
            }
        }
        __syncthreads();
    }
}

// ---------------- launch -----------------------------------------------------
extern "C" void kernel_launch(void* const* d_in, const int* in_sizes, int n_in,
                              void* d_out, int out_size)
{
    const float* x    = (const float*)d_in[0];
    const int*   ei   = (const int*)  d_in[1];
    const float* W_l1 = (const float*)d_in[2];
    const float* W_r1 = (const float*)d_in[3];
    const float* b1   = (const float*)d_in[4];
    const float* W_l2 = (const float*)d_in[5];
    const float* W_r2 = (const float*)d_in[6];
    const float* b2   = (const float*)d_in[7];
    float*       out  = (float*)d_out;

    int n = in_sizes[0] / F_IN;
    int e = in_sizes[1] / 2;
    const int* srcp = ei;
    const int* dstp = ei + e;

    __nv_bfloat16 *a1h, *a1l, *a2h, *a2l, *bt1h, *bt1l, *bt2h, *bt2l;
    float *t_p, *u_p;
    cudaGetSymbolAddress((void**)&a1h,  g_A1hi);
    cudaGetSymbolAddress((void**)&a1l,  g_A1lo);
    cudaGetSymbolAddress((void**)&a2h,  g_A2hi);
    cudaGetSymbolAddress((void**)&a2l,  g_A2lo);
    cudaGetSymbolAddress((void**)&bt1h, g_Bt1_hi);
    cudaGetSymbolAddress((void**)&bt1l, g_Bt1_lo);
    cudaGetSymbolAddress((void**)&bt2h, g_Bt2_hi);
    cudaGetSymbolAddress((void**)&bt2l, g_Bt2_lo);
    cudaGetSymbolAddress((void**)&t_p,  g_t);
    cudaGetSymbolAddress((void**)&u_p,  g_u);

    cudaFuncSetAttribute(gemm1_kernel, cudaFuncAttributeMaxDynamicSharedMemorySize, SMEM_GEMM1);
    cudaFuncSetAttribute(gemm2_kernel, cudaFuncAttributeMaxDynamicSharedMemorySize, SMEM_GEMM2);

    int mtiles = (n + 127) / 128;

    // CSR build + weight prep (fused persistent kernel)
    csr_coop_kernel<<<GSYNC_BLOCKS, 256>>>(srcp, dstp, W_l1, W_r1, W_l2, W_r2, e, n); // 0
    // layer-1 aggregation + x convert
    agg128_kernel<<<(n * 32 + 255) / 256, 256>>>(x);                     // 1
    // h = relu([agg1|x] @ [W_l1;W_r1] + b1) -> A2 hi/lo
    gemm1_kernel<<<dim3(mtiles, 4), 256, SMEM_GEMM1>>>(a1h, a1l, bt1h, bt1l, b1,
                                                       a2h, a2l, n);     // 2
    // [t|u] = h @ [W_l2|W_r2]
    gemm2_kernel<<<mtiles, 256, SMEM_GEMM2>>>(a2h, a2l, bt2h, bt2l, t_p, u_p, n); // 3 (profiled)
    // layer-2 aggregation of t + sigmoid epilogue (unroll-4)
    agg64_final_kernel<<<(n * 32 + 255) / 256, 256>>>(b2, out);          // 4
}